// round 15
// baseline (speedup 1.0000x reference)
#include <cuda_runtime.h>
#include <cuda_fp16.h>
#include <cstdint>

// Problem constants
#define D     768
#define OUTD  5120
#define NSEG  10000
#define NMAX  100000
#define KREL  1536
#define KENT  768
#define SEG_CAP 512                           // smem score capacity per segment

// GEMM tiling
#define BM 128
#define BN 256
#define BK 64
#define PITCH 72                              // halves per row (144 B), conflict-free
#define MATA (128 * PITCH * 2)                // 18432 B
#define MATB (256 * PITCH * 2)                // 36864 B
#define STAGE_SZ (MATA + MATB)                // 55296 B
#define NSTAGE 3
#define SMEM_TOT (NSTAGE * STAGE_SZ)          // 165888 B

// ---------------- device scratch (no allocations allowed) ----------------
__device__ float g_score[NMAX];               // only used for segments > SEG_CAP

__device__ __half g_A_rel[(size_t)NSEG * KREL];
__device__ __half g_A_ent[(size_t)NSEG * KENT];
__device__ __half g_W_rel[(size_t)OUTD * KREL];
__device__ __half g_W_ent[(size_t)OUTD * KENT];

// ---------------- PTX helpers ----------------
__device__ __forceinline__ uint32_t smem_u32(const void* p) {
    uint32_t a;
    asm("{ .reg .u64 t; cvta.to.shared.u64 t, %1; cvt.u32.u64 %0, t; }"
        : "=r"(a) : "l"(p));
    return a;
}

#define CP16(dst, src, sz) \
    asm volatile("cp.async.cg.shared.global [%0], [%1], 16, %2;" \
                 :: "r"(dst), "l"(src), "r"(sz) : "memory")
#define CP_COMMIT() asm volatile("cp.async.commit_group;" ::: "memory")
#define CP_WAIT(n)  asm volatile("cp.async.wait_group %0;" :: "n"(n) : "memory")

#define LDSM_X4(r0, r1, r2, r3, addr)                                     \
    asm volatile("ldmatrix.sync.aligned.m8n8.x4.shared.b16 "              \
                 "{%0,%1,%2,%3}, [%4];"                                   \
                 : "=r"(r0), "=r"(r1), "=r"(r2), "=r"(r3) : "r"(addr))

#define MMA16816(c, a, b)                                                 \
    asm volatile("mma.sync.aligned.m16n8k16.row.col.f32.f16.f16.f32 "     \
                 "{%0,%1,%2,%3}, {%4,%5,%6,%7}, {%8,%9}, {%0,%1,%2,%3};"  \
                 : "+f"((c)[0]), "+f"((c)[1]), "+f"((c)[2]), "+f"((c)[3]) \
                 : "r"((a)[0]), "r"((a)[1]), "r"((a)[2]), "r"((a)[3]),    \
                   "r"((b)[0]), "r"((b)[1]))

// ---------------- fp32 -> fp16 round (both weight matrices, one launch) ----------------
__global__ void k_round2(const float* __restrict__ srcR, __half* __restrict__ dstR,
                         size_t nR,
                         const float* __restrict__ srcE, __half* __restrict__ dstE,
                         size_t nE) {
    size_t i = (size_t)blockIdx.x * blockDim.x + threadIdx.x;
    if (i < nR) dstR[i] = __float2half_rn(srcR[i]);
    size_t j = i - nR;
    if (i >= nR && j < nE) dstE[j] = __float2half_rn(srcE[j]);
}

// ---------------- fused: bounds + score + segment softmax + aggregation ----------------
// One 256-thread block per segment. Deterministic.
__global__ __launch_bounds__(256)
void k_fused(const float* __restrict__ P,
             const float* __restrict__ Ent,
             const float* __restrict__ Nbr,
             const float* __restrict__ Rel,
             const float* __restrict__ Ctab,
             const float* __restrict__ sW,
             const float* __restrict__ sbias,
             const int*   __restrict__ counts,
             const int*   __restrict__ pidx,
             const int*   __restrict__ eidx,
             int n)
{
    const int e    = blockIdx.x;
    const int tid  = threadIdx.x;          // 256
    const int lane = tid & 31;
    const int warp = tid >> 5;             // 0..7

    __shared__ int   sh_s, sh_t;
    __shared__ float sh_w[SEG_CAP];        // scores, then normalized weights
    __shared__ float sh_mx, sh_invd;

    // ---- segment bounds via binary search on sorted eidx ----
    if (tid == 0) {
        int lo = 0, hi = n;
        while (lo < hi) { int m = (lo + hi) >> 1; if (eidx[m] < e) lo = m + 1; else hi = m; }
        sh_s = lo;
        hi = n;
        while (lo < hi) { int m = (lo + hi) >> 1; if (eidx[m] < e + 1) lo = m + 1; else hi = m; }
        sh_t = lo;
    }
    __syncthreads();
    const int s = sh_s, t = sh_t;
    const int len = t - s;
    const bool big = (len > SEG_CAP);

    float aR[6] = {0.f, 0.f, 0.f, 0.f, 0.f, 0.f};
    float aE[3] = {0.f, 0.f, 0.f};
    float inv_len = 0.f;

    if (len > 0) {
        // ---- phase 1: score each edge (one warp per edge, round-robin) ----
        const float4* W4 = (const float4*)sW;
        for (int j = s + warp; j < t; j += 8) {
            const float4* r0 = (const float4*)(P    + (size_t)pidx[j]   * D);
            const float4* r1 = (const float4*)(Ent  + (size_t)j         * D);
            const float4* r2 = (const float4*)(Nbr  + (size_t)j         * D);
            const float4* r3 = (const float4*)(Rel  + (size_t)j         * D);
            const float4* r4 = (const float4*)(Ctab + (size_t)counts[j] * D);

            float sc = 0.f;
            #pragma unroll 2
            for (int i = lane; i < D / 4; i += 32) {
                float4 x, w;
                x = r0[i]; w = W4[i      ]; sc += x.x*w.x + x.y*w.y + x.z*w.z + x.w*w.w;
                x = r1[i]; w = W4[i + 192]; sc += x.x*w.x + x.y*w.y + x.z*w.z + x.w*w.w;
                x = r2[i]; w = W4[i + 384]; sc += x.x*w.x + x.y*w.y + x.z*w.z + x.w*w.w;
                x = r3[i]; w = W4[i + 576]; sc += x.x*w.x + x.y*w.y + x.z*w.z + x.w*w.w;
                x = r4[i]; w = W4[i + 768]; sc += x.x*w.x + x.y*w.y + x.z*w.z + x.w*w.w;
            }
            #pragma unroll
            for (int o = 16; o; o >>= 1) sc += __shfl_xor_sync(0xffffffffu, sc, o);
            if (lane == 0) {
                sc += sbias[0];
                if (big) g_score[j] = sc; else sh_w[j - s] = sc;
            }
        }
        __syncthreads();

        // ---- phase 2: softmax normalization (warp 0) ----
        if (warp == 0) {
            float m = -3.402823466e38f;
            if (big) { for (int i = lane; i < len; i += 32) m = fmaxf(m, g_score[s + i]); }
            else     { for (int i = lane; i < len; i += 32) m = fmaxf(m, sh_w[i]); }
            #pragma unroll
            for (int o = 16; o; o >>= 1) m = fmaxf(m, __shfl_xor_sync(0xffffffffu, m, o));
            float d = 0.f;
            if (big) { for (int i = lane; i < len; i += 32) d += expf(g_score[s + i] - m); }
            else     { for (int i = lane; i < len; i += 32) d += expf(sh_w[i] - m); }
            #pragma unroll
            for (int o = 16; o; o >>= 1) d += __shfl_xor_sync(0xffffffffu, d, o);
            float invd = 1.f / d;
            if (!big)
                for (int i = lane; i < len; i += 32)
                    sh_w[i] = expf(sh_w[i] - m) * invd;
            if (lane == 0) { sh_mx = m; sh_invd = invd; }
        }
        __syncthreads();
        const float mx = sh_mx, invd = sh_invd;

        // ---- phase 3: weighted aggregation (rows L2-warm from phase 1) ----
        for (int j = s; j < t; j++) {
            float w = big ? expf(g_score[j] - mx) * invd : sh_w[j - s];
            const float* rr = Rel  + (size_t)j * D;
            const float* cr = Ctab + (size_t)counts[j] * D;
            const float* er = Ent  + (size_t)j * D;
            aR[0] += w * rr[tid      ];
            aR[1] += w * rr[tid + 256];
            aR[2] += w * rr[tid + 512];
            aR[3] += w * cr[tid      ];
            aR[4] += w * cr[tid + 256];
            aR[5] += w * cr[tid + 512];
            aE[0] += er[tid      ];
            aE[1] += er[tid + 256];
            aE[2] += er[tid + 512];
        }
        inv_len = 1.f / (float)len;
    }

    size_t baseR = (size_t)e * (2 * D);
    size_t baseE = (size_t)e * D;
    #pragma unroll
    for (int q = 0; q < 6; q++)
        g_A_rel[baseR + tid + q * 256] = __float2half_rn(aR[q]);
    #pragma unroll
    for (int q = 0; q < 3; q++)
        g_A_ent[baseE + tid + q * 256] = __float2half_rn(aE[q] * inv_len);
}

// ---------------- HMMA GEMM (both projections in one launch via blockIdx.z)
// C[M,5120] = A16[M,K] @ W16[5120,K]^T + bias. mma.sync m16n8k16, fp32 acc.
// 256 threads = 8 warps as 4(m) x 2(n); warp tile 32x128. BK=64, 3-stage cp.async,
// single __syncthreads per k-iteration.
__global__ __launch_bounds__(256, 1)
void k_gemm_f16(const __half* __restrict__ A_rel, const __half* __restrict__ W_rel,
                const float* __restrict__ b_rel,  float* __restrict__ C_rel,
                const __half* __restrict__ A_ent, const __half* __restrict__ W_ent,
                const float* __restrict__ b_ent,  float* __restrict__ C_ent,
                int M)
{
    const int z = blockIdx.z;
    const __half* A16 = z ? A_ent : A_rel;
    const __half* W16 = z ? W_ent : W_rel;
    const float*  bias = z ? b_ent : b_rel;
    float*        C    = z ? C_ent : C_rel;
    const int K = z ? KENT : KREL;

    extern __shared__ char smem[];
    uint32_t sbase = smem_u32(smem);
    const int tid  = threadIdx.x;
    const int lane = tid & 31;
    const int wid  = tid >> 5;
    const int wm   = wid >> 1;          // 0..3  -> m offset wm*32
    const int wn   = wid & 1;           // 0..1  -> n offset wn*128
    const int m0 = blockIdx.y * BM;
    const int n0 = blockIdx.x * BN;
    const int KT = K / BK;

    // ldmatrix source coordinates (fixed per thread)
    const int a_row = wm * 32 + (lane & 15);
    const int a_col = (lane >> 4) * 8;                              // halves
    const int b_row = wn * 128 + ((lane >> 4) << 3) + (lane & 7);
    const int b_col = ((lane >> 3) & 1) * 8;                        // halves

    float acc[2][16][4];
    #pragma unroll
    for (int i = 0; i < 2; i++)
        #pragma unroll
        for (int j = 0; j < 16; j++)
            #pragma unroll
            for (int q = 0; q < 4; q++) acc[i][j][q] = 0.f;

    // ---- stage loader: A | B, pitch 72 halves (144 B) ----
    auto load_tile = [&](int kt, int st) {
        uint32_t sb = sbase + st * STAGE_SZ;
        int k0 = kt * BK;
        #pragma unroll
        for (int it = 0; it < 4; it++) {               // A: 1024 chunks of 16B
            int c = it * 256 + tid;
            int r = c >> 3, q = c & 7;
            int gm = m0 + r;
            int ok = (gm < M);
            size_t go = (size_t)(ok ? gm : 0) * K + k0 + q * 8;
            uint32_t off = (uint32_t)(r * 144 + q * 16);
            CP16(sb + off, A16 + go, ok ? 16 : 0);
        }
        uint32_t bb = sb + MATA;
        #pragma unroll
        for (int it = 0; it < 8; it++) {               // B: 2048 chunks of 16B
            int c = it * 256 + tid;
            int r = c >> 3, q = c & 7;
            size_t go = (size_t)(n0 + r) * K + k0 + q * 8;
            uint32_t off = (uint32_t)(r * 144 + q * 16);
            CP16(bb + off, W16 + go, 16);
        }
        CP_COMMIT();
    };

    // prologue: 2 stages in flight (KT >= 12 always here)
    load_tile(0, 0);
    load_tile(1, 1);

    for (int kt = 0; kt < KT; kt++) {
        int st = kt % NSTAGE;
        CP_WAIT(1);                 // stage kt's group complete
        __syncthreads();            // orders prior reads before overwrite below

        if (kt + 2 < KT) load_tile(kt + 2, (kt + 2) % NSTAGE);
        else CP_COMMIT();           // keep group accounting uniform

        uint32_t sA = sbase + st * STAGE_SZ;
        uint32_t sB = sA + MATA;

        #pragma unroll
        for (int ks = 0; ks < 4; ks++) {
            const int kk = ks * 16;
            uint32_t ah[2][4];

            uint32_t aoff = (uint32_t)(a_row * 144 + (kk + a_col) * 2);
            #pragma unroll
            for (int i = 0; i < 2; i++) {
                uint32_t ad = sA + aoff + (uint32_t)(i * 16 * 144);
                LDSM_X4(ah[i][0], ah[i][1], ah[i][2], ah[i][3], ad);
            }
            uint32_t boff = (uint32_t)(b_row * 144 + (kk + b_col) * 2);
            #pragma unroll
            for (int jp = 0; jp < 8; jp++) {
                uint32_t bh[2][2];
                uint32_t bd = sB + boff + (uint32_t)(jp * 16 * 144);
                LDSM_X4(bh[0][0], bh[0][1], bh[1][0], bh[1][1], bd);
                #pragma unroll
                for (int i = 0; i < 2; i++)
                    #pragma unroll
                    for (int jj = 0; jj < 2; jj++) {
                        int j = jp * 2 + jj;
                        MMA16816(acc[i][j], ah[i], bh[jj]);
                    }
            }
        }
    }

    // ---- epilogue: bias + store ----
    const int row_base = m0 + wm * 32 + (lane >> 2);
    #pragma unroll
    for (int i = 0; i < 2; i++) {
        int r0 = row_base + i * 16;
        int r1 = r0 + 8;
        #pragma unroll
        for (int j = 0; j < 16; j++) {
            int col = n0 + wn * 128 + j * 8 + (lane & 3) * 2;
            float2 bv = *(const float2*)(bias + col);
            if (r0 < M) {
                float2 v = make_float2(acc[i][j][0] + bv.x, acc[i][j][1] + bv.y);
                *(float2*)(C + (size_t)r0 * OUTD + col) = v;
            }
            if (r1 < M) {
                float2 v = make_float2(acc[i][j][2] + bv.x, acc[i][j][3] + bv.y);
                *(float2*)(C + (size_t)r1 * OUTD + col) = v;
            }
        }
    }
}

// ---------------- launch ----------------
extern "C" void kernel_launch(void* const* d_in, const int* in_sizes, int n_in,
                              void* d_out, int out_size)
{
    const float* prompt = (const float*)d_in[0];
    const float* ent    = (const float*)d_in[1];
    const float* nbr    = (const float*)d_in[2];
    const float* rel    = (const float*)d_in[3];
    const float* ctab   = (const float*)d_in[4];
    const float* sW     = (const float*)d_in[5];
    const float* sb     = (const float*)d_in[6];
    const float* relW   = (const float*)d_in[7];
    const float* relb   = (const float*)d_in[8];
    const float* entW   = (const float*)d_in[9];
    const float* entb   = (const float*)d_in[10];
    const int*   counts = (const int*)d_in[11];
    const int*   pidx   = (const int*)d_in[12];
    const int*   eidx   = (const int*)d_in[13];
    int N = in_sizes[11];

    float* rel_out = (float*)d_out;
    float* ent_out = rel_out + (size_t)NSEG * OUTD;

    void *pAR, *pAE, *pWR, *pWE;
    cudaGetSymbolAddress(&pAR, g_A_rel);
    cudaGetSymbolAddress(&pAE, g_A_ent);
    cudaGetSymbolAddress(&pWR, g_W_rel);
    cudaGetSymbolAddress(&pWE, g_W_ent);

    cudaFuncSetAttribute(k_gemm_f16,
                         cudaFuncAttributeMaxDynamicSharedMemorySize, SMEM_TOT);

    // weight rounding (independent of everything else)
    {
        size_t nR = (size_t)OUTD * KREL, nE = (size_t)OUTD * KENT;
        size_t tot = nR + nE;
        k_round2<<<(unsigned)((tot + 255) / 256), 256>>>(relW, (__half*)pWR, nR,
                                                         entW, (__half*)pWE, nE);
    }

    k_fused<<<NSEG, 256>>>(prompt, ent, nbr, rel, ctab, sW, sb,
                           counts, pidx, eidx, N);

    dim3 grid(OUTD / BN, (NSEG + BM - 1) / BM, 2);
    k_gemm_f16<<<grid, 256, SMEM_TOT>>>(
        (const __half*)pAR, (const __half*)pWR, relb, rel_out,
        (const __half*)pAE, (const __half*)pWE, entb, ent_out, NSEG);
}

// round 16
// speedup vs baseline: 1.1185x; 1.1185x over previous
#include <cuda_runtime.h>
#include <cuda_fp16.h>
#include <cstdint>

// Problem constants
#define D     768
#define OUTD  5120
#define NSEG  10000
#define NMAX  100000
#define KREL  1536
#define KENT  768

// GEMM tiling: 2 CTAs/SM
#define BM 128
#define BN 128
#define BK 64
#define PITCH 72                              // halves per row (144 B), conflict-free
#define MATA (128 * PITCH * 2)                // 18432 B
#define MATB (128 * PITCH * 2)                // 18432 B
#define STAGE_SZ (MATA + MATB)                // 36864 B
#define NSTAGE 3
#define SMEM_TOT (NSTAGE * STAGE_SZ)          // 110592 B per CTA

// ---------------- device scratch (no allocations allowed) ----------------
__device__ float g_score[NMAX];
__device__ int   g_seg_start[NSEG];
__device__ int   g_seg_end[NSEG];

__device__ __half g_A_rel[(size_t)NSEG * KREL];
__device__ __half g_A_ent[(size_t)NSEG * KENT];
__device__ __half g_W_rel[(size_t)OUTD * KREL];
__device__ __half g_W_ent[(size_t)OUTD * KENT];

// ---------------- PTX helpers ----------------
__device__ __forceinline__ uint32_t smem_u32(const void* p) {
    uint32_t a;
    asm("{ .reg .u64 t; cvta.to.shared.u64 t, %1; cvt.u32.u64 %0, t; }"
        : "=r"(a) : "l"(p));
    return a;
}

#define CP16(dst, src, sz) \
    asm volatile("cp.async.cg.shared.global [%0], [%1], 16, %2;" \
                 :: "r"(dst), "l"(src), "r"(sz) : "memory")
#define CP_COMMIT() asm volatile("cp.async.commit_group;" ::: "memory")
#define CP_WAIT(n)  asm volatile("cp.async.wait_group %0;" :: "n"(n) : "memory")

#define LDSM_X4(r0, r1, r2, r3, addr)                                     \
    asm volatile("ldmatrix.sync.aligned.m8n8.x4.shared.b16 "              \
                 "{%0,%1,%2,%3}, [%4];"                                   \
                 : "=r"(r0), "=r"(r1), "=r"(r2), "=r"(r3) : "r"(addr))

#define MMA16816(c, a, b)                                                 \
    asm volatile("mma.sync.aligned.m16n8k16.row.col.f32.f16.f16.f32 "     \
                 "{%0,%1,%2,%3}, {%4,%5,%6,%7}, {%8,%9}, {%0,%1,%2,%3};"  \
                 : "+f"((c)[0]), "+f"((c)[1]), "+f"((c)[2]), "+f"((c)[3]) \
                 : "r"((a)[0]), "r"((a)[1]), "r"((a)[2]), "r"((a)[3]),    \
                   "r"((b)[0]), "r"((b)[1]))

// ---------------- segment bounds ----------------
__global__ void k_init_bounds() {
    int e = blockIdx.x * blockDim.x + threadIdx.x;
    if (e < NSEG) { g_seg_start[e] = 0; g_seg_end[e] = 0; }
}

__global__ void k_bounds(const int* __restrict__ ei, int n) {
    int i = blockIdx.x * blockDim.x + threadIdx.x;
    if (i >= n) return;
    int e = ei[i];
    if (i == 0     || ei[i - 1] != e) g_seg_start[e] = i;
    if (i == n - 1 || ei[i + 1] != e) g_seg_end[e]   = i + 1;
}

// ---------------- fp32 -> fp16 round, vectorized (both weights, one launch) ----
// nR, nE divisible by 4.
__global__ void k_round2(const float4* __restrict__ srcR, uint2* __restrict__ dstR,
                         size_t nR4,
                         const float4* __restrict__ srcE, uint2* __restrict__ dstE,
                         size_t nE4) {
    size_t i = (size_t)blockIdx.x * blockDim.x + threadIdx.x;
    if (i < nR4) {
        float4 v = srcR[i];
        __half2 lo = __floats2half2_rn(v.x, v.y);
        __half2 hi = __floats2half2_rn(v.z, v.w);
        dstR[i] = make_uint2(*(uint32_t*)&lo, *(uint32_t*)&hi);
    } else {
        size_t j = i - nR4;
        if (j < nE4) {
            float4 v = srcE[j];
            __half2 lo = __floats2half2_rn(v.x, v.y);
            __half2 hi = __floats2half2_rn(v.z, v.w);
            dstE[j] = make_uint2(*(uint32_t*)&lo, *(uint32_t*)&hi);
        }
    }
}

// ---------------- per-edge scorer: one warp per edge ----------------
__global__ void k_score(const float* __restrict__ P,
                        const float* __restrict__ Ent,
                        const float* __restrict__ Nbr,
                        const float* __restrict__ Rel,
                        const float* __restrict__ Ctab,
                        const float* __restrict__ W,
                        const float* __restrict__ bias,
                        const int*   __restrict__ counts,
                        const int*   __restrict__ pidx,
                        int n)
{
    int gw   = (blockIdx.x * blockDim.x + threadIdx.x) >> 5;
    int lane = threadIdx.x & 31;
    if (gw >= n) return;

    const float4* r0 = (const float4*)(P    + (size_t)pidx[gw]   * D);
    const float4* r1 = (const float4*)(Ent  + (size_t)gw         * D);
    const float4* r2 = (const float4*)(Nbr  + (size_t)gw         * D);
    const float4* r3 = (const float4*)(Rel  + (size_t)gw         * D);
    const float4* r4 = (const float4*)(Ctab + (size_t)counts[gw] * D);
    const float4* W4 = (const float4*)W;

    float s = 0.f;
    #pragma unroll 2
    for (int i = lane; i < D / 4; i += 32) {
        float4 x, w;
        x = r0[i]; w = W4[i      ]; s += x.x*w.x + x.y*w.y + x.z*w.z + x.w*w.w;
        x = r1[i]; w = W4[i + 192]; s += x.x*w.x + x.y*w.y + x.z*w.z + x.w*w.w;
        x = r2[i]; w = W4[i + 384]; s += x.x*w.x + x.y*w.y + x.z*w.z + x.w*w.w;
        x = r3[i]; w = W4[i + 576]; s += x.x*w.x + x.y*w.y + x.z*w.z + x.w*w.w;
        x = r4[i]; w = W4[i + 768]; s += x.x*w.x + x.y*w.y + x.z*w.z + x.w*w.w;
    }
    #pragma unroll
    for (int o = 16; o; o >>= 1) s += __shfl_xor_sync(0xffffffffu, s, o);
    if (lane == 0) g_score[gw] = s + bias[0];
}

// ---------------- fused segment softmax + aggregation; writes fp16 ----------------
__global__ void k_segagg(const float* __restrict__ Ent,
                         const float* __restrict__ Rel,
                         const float* __restrict__ Ctab,
                         const int*   __restrict__ counts)
{
    int e   = blockIdx.x;
    int tid = threadIdx.x;  // 256
    int s = g_seg_start[e], t = g_seg_end[e];

    float aR[6] = {0.f, 0.f, 0.f, 0.f, 0.f, 0.f};
    float aE[3] = {0.f, 0.f, 0.f};
    float inv_len = 0.f;

    if (s < t) {
        __shared__ float sh_mx, sh_den;
        if (tid < 32) {
            float m = -3.402823466e38f;
            for (int j = s + tid; j < t; j += 32) m = fmaxf(m, g_score[j]);
            #pragma unroll
            for (int o = 16; o; o >>= 1) m = fmaxf(m, __shfl_xor_sync(0xffffffffu, m, o));
            float d = 0.f;
            for (int j = s + tid; j < t; j += 32) d += expf(g_score[j] - m);
            #pragma unroll
            for (int o = 16; o; o >>= 1) d += __shfl_xor_sync(0xffffffffu, d, o);
            if (tid == 0) { sh_mx = m; sh_den = d; }
        }
        __syncthreads();
        float mx   = sh_mx;
        float invd = 1.f / sh_den;

        for (int j = s; j < t; j++) {
            float w = expf(g_score[j] - mx) * invd;
            const float* rr = Rel  + (size_t)j * D;
            const float* cr = Ctab + (size_t)counts[j] * D;
            const float* er = Ent  + (size_t)j * D;
            aR[0] += w * rr[tid      ];
            aR[1] += w * rr[tid + 256];
            aR[2] += w * rr[tid + 512];
            aR[3] += w * cr[tid      ];
            aR[4] += w * cr[tid + 256];
            aR[5] += w * cr[tid + 512];
            aE[0] += er[tid      ];
            aE[1] += er[tid + 256];
            aE[2] += er[tid + 512];
        }
        inv_len = 1.f / (float)(t - s);
    }

    size_t baseR = (size_t)e * (2 * D);
    size_t baseE = (size_t)e * D;
    #pragma unroll
    for (int q = 0; q < 6; q++)
        g_A_rel[baseR + tid + q * 256] = __float2half_rn(aR[q]);
    #pragma unroll
    for (int q = 0; q < 3; q++)
        g_A_ent[baseE + tid + q * 256] = __float2half_rn(aE[q] * inv_len);
}

// ---------------- HMMA GEMM (both projections in one launch via blockIdx.z)
// C[M,5120] = A16[M,K] @ W16[5120,K]^T + bias. mma.sync m16n8k16, fp32 acc.
// 256 threads = 8 warps as 4(m) x 2(n); warp tile 32x64. BK=64, 3-stage cp.async,
// single __syncthreads per k-iteration, 2 CTAs/SM for bubble overlap.
__global__ __launch_bounds__(256, 2)
void k_gemm_f16(const __half* __restrict__ A_rel, const __half* __restrict__ W_rel,
                const float* __restrict__ b_rel,  float* __restrict__ C_rel,
                const __half* __restrict__ A_ent, const __half* __restrict__ W_ent,
                const float* __restrict__ b_ent,  float* __restrict__ C_ent,
                int M)
{
    const int z = blockIdx.z;
    const __half* A16 = z ? A_ent : A_rel;
    const __half* W16 = z ? W_ent : W_rel;
    const float*  bias = z ? b_ent : b_rel;
    float*        C    = z ? C_ent : C_rel;
    const int K = z ? KENT : KREL;

    extern __shared__ char smem[];
    uint32_t sbase = smem_u32(smem);
    const int tid  = threadIdx.x;
    const int lane = tid & 31;
    const int wid  = tid >> 5;
    const int wm   = wid >> 1;          // 0..3  -> m offset wm*32
    const int wn   = wid & 1;           // 0..1  -> n offset wn*64
    const int m0 = blockIdx.y * BM;
    const int n0 = blockIdx.x * BN;
    const int KT = K / BK;

    // ldmatrix source coordinates (fixed per thread)
    const int a_row = wm * 32 + (lane & 15);
    const int a_col = (lane >> 4) * 8;                              // halves
    const int b_row = wn * 64 + ((lane >> 4) << 3) + (lane & 7);
    const int b_col = ((lane >> 3) & 1) * 8;                        // halves

    float acc[2][8][4];
    #pragma unroll
    for (int i = 0; i < 2; i++)
        #pragma unroll
        for (int j = 0; j < 8; j++)
            #pragma unroll
            for (int q = 0; q < 4; q++) acc[i][j][q] = 0.f;

    // ---- stage loader: A | B, pitch 72 halves (144 B) ----
    auto load_tile = [&](int kt, int st) {
        uint32_t sb = sbase + st * STAGE_SZ;
        int k0 = kt * BK;
        #pragma unroll
        for (int it = 0; it < 4; it++) {               // A: 1024 chunks of 16B
            int c = it * 256 + tid;
            int r = c >> 3, q = c & 7;
            int gm = m0 + r;
            int ok = (gm < M);
            size_t go = (size_t)(ok ? gm : 0) * K + k0 + q * 8;
            uint32_t off = (uint32_t)(r * 144 + q * 16);
            CP16(sb + off, A16 + go, ok ? 16 : 0);
        }
        uint32_t bb = sb + MATA;
        #pragma unroll
        for (int it = 0; it < 4; it++) {               // B: 1024 chunks of 16B
            int c = it * 256 + tid;
            int r = c >> 3, q = c & 7;
            size_t go = (size_t)(n0 + r) * K + k0 + q * 8;
            uint32_t off = (uint32_t)(r * 144 + q * 16);
            CP16(bb + off, W16 + go, 16);
        }
        CP_COMMIT();
    };

    // prologue: 2 stages in flight (KT >= 12 always here)
    load_tile(0, 0);
    load_tile(1, 1);

    for (int kt = 0; kt < KT; kt++) {
        int st = kt % NSTAGE;
        CP_WAIT(1);                 // stage kt's group complete
        __syncthreads();            // orders prior reads before overwrite below

        if (kt + 2 < KT) load_tile(kt + 2, (kt + 2) % NSTAGE);
        else CP_COMMIT();           // keep group accounting uniform

        uint32_t sA = sbase + st * STAGE_SZ;
        uint32_t sB = sA + MATA;

        #pragma unroll
        for (int ks = 0; ks < 4; ks++) {
            const int kk = ks * 16;
            uint32_t ah[2][4];

            uint32_t aoff = (uint32_t)(a_row * 144 + (kk + a_col) * 2);
            #pragma unroll
            for (int i = 0; i < 2; i++) {
                uint32_t ad = sA + aoff + (uint32_t)(i * 16 * 144);
                LDSM_X4(ah[i][0], ah[i][1], ah[i][2], ah[i][3], ad);
            }
            uint32_t boff = (uint32_t)(b_row * 144 + (kk + b_col) * 2);
            #pragma unroll
            for (int jp = 0; jp < 4; jp++) {
                uint32_t bh[2][2];
                uint32_t bd = sB + boff + (uint32_t)(jp * 16 * 144);
                LDSM_X4(bh[0][0], bh[0][1], bh[1][0], bh[1][1], bd);
                #pragma unroll
                for (int i = 0; i < 2; i++)
                    #pragma unroll
                    for (int jj = 0; jj < 2; jj++) {
                        int j = jp * 2 + jj;
                        MMA16816(acc[i][j], ah[i], bh[jj]);
                    }
            }
        }
    }

    // ---- epilogue: bias + store ----
    const int row_base = m0 + wm * 32 + (lane >> 2);
    #pragma unroll
    for (int i = 0; i < 2; i++) {
        int r0 = row_base + i * 16;
        int r1 = r0 + 8;
        #pragma unroll
        for (int j = 0; j < 8; j++) {
            int col = n0 + wn * 64 + j * 8 + (lane & 3) * 2;
            float2 bv = *(const float2*)(bias + col);
            if (r0 < M) {
                float2 v = make_float2(acc[i][j][0] + bv.x, acc[i][j][1] + bv.y);
                *(float2*)(C + (size_t)r0 * OUTD + col) = v;
            }
            if (r1 < M) {
                float2 v = make_float2(acc[i][j][2] + bv.x, acc[i][j][3] + bv.y);
                *(float2*)(C + (size_t)r1 * OUTD + col) = v;
            }
        }
    }
}

// ---------------- launch ----------------
extern "C" void kernel_launch(void* const* d_in, const int* in_sizes, int n_in,
                              void* d_out, int out_size)
{
    const float* prompt = (const float*)d_in[0];
    const float* ent    = (const float*)d_in[1];
    const float* nbr    = (const float*)d_in[2];
    const float* rel    = (const float*)d_in[3];
    const float* ctab   = (const float*)d_in[4];
    const float* sW     = (const float*)d_in[5];
    const float* sb     = (const float*)d_in[6];
    const float* relW   = (const float*)d_in[7];
    const float* relb   = (const float*)d_in[8];
    const float* entW   = (const float*)d_in[9];
    const float* entb   = (const float*)d_in[10];
    const int*   counts = (const int*)d_in[11];
    const int*   pidx   = (const int*)d_in[12];
    const int*   eidx   = (const int*)d_in[13];
    int N = in_sizes[11];

    float* rel_out = (float*)d_out;
    float* ent_out = rel_out + (size_t)NSEG * OUTD;

    void *pAR, *pAE, *pWR, *pWE;
    cudaGetSymbolAddress(&pAR, g_A_rel);
    cudaGetSymbolAddress(&pAE, g_A_ent);
    cudaGetSymbolAddress(&pWR, g_W_rel);
    cudaGetSymbolAddress(&pWE, g_W_ent);

    cudaFuncSetAttribute(k_gemm_f16,
                         cudaFuncAttributeMaxDynamicSharedMemorySize, SMEM_TOT);

    // weight rounding, vectorized (independent of everything else)
    {
        size_t nR4 = (size_t)OUTD * KREL / 4, nE4 = (size_t)OUTD * KENT / 4;
        size_t tot = nR4 + nE4;
        k_round2<<<(unsigned)((tot + 255) / 256), 256>>>(
            (const float4*)relW, (uint2*)pWR, nR4,
            (const float4*)entW, (uint2*)pWE, nE4);
    }

    k_init_bounds<<<(NSEG + 255) / 256, 256>>>();
    k_bounds<<<(N + 255) / 256, 256>>>(eidx, N);
    k_score<<<(N + 7) / 8, 256>>>(prompt, ent, nbr, rel, ctab, sW, sb, counts, pidx, N);
    k_segagg<<<NSEG, 256>>>(ent, rel, ctab, counts);

    dim3 grid(OUTD / BN, (NSEG + BM - 1) / BM, 2);
    k_gemm_f16<<<grid, 256, SMEM_TOT>>>(
        (const __half*)pAR, (const __half*)pWR, relb, rel_out,
        (const __half*)pAE, (const __half*)pWE, entb, ent_out, NSEG);
}